// round 1
// baseline (speedup 1.0000x reference)
#include <cuda_runtime.h>
#include <cuda_bf16.h>
#include <math.h>

// ---------------------------------------------------------------------------
// Problem constants (B=4, C=128, H=W=128, NH=8, d=16, GDFN hidden=512)
// ---------------------------------------------------------------------------
#define BATCH 4
#define CH    128
#define HW    16384          // 128*128
#define NHEAD 8
#define DHEAD 16

// ---------------------------------------------------------------------------
// Scratch (device globals; no allocation allowed)
// ---------------------------------------------------------------------------
__device__ float g_bufA[BATCH * 512 * HW];   // qkv_pre / g1 output (max 512 ch)
__device__ float g_bufB[BATCH * 512 * HW];   // qkv (post dw) / hdn (post dw)
__device__ float g_out [BATCH * CH  * HW];   // attention output (b,c,hw)
__device__ float g_mu  [BATCH * HW];
__device__ float g_rstd[BATCH * HW];
__device__ float g_partS [32 * 8 * 256];     // partial logits  [bh][seg][16*16]
__device__ float g_partQ2[32 * 8 * 16];      // partial ||q||^2 [bh][seg][i]
__device__ float g_partK2[32 * 8 * 16];      // partial ||k||^2 [bh][seg][j]
__device__ float g_attn  [32 * 256];         // softmaxed attn  [bh][16*16]

// ---------------------------------------------------------------------------
// 1) Per-pixel LayerNorm stats over C=128 channels
// ---------------------------------------------------------------------------
__global__ __launch_bounds__(256) void ln_stats_k(const float* __restrict__ x,
                                                  float* __restrict__ mu,
                                                  float* __restrict__ rstd)
{
    int b = blockIdx.y;
    int n = blockIdx.x * 256 + threadIdx.x;
    const float* xb = x + (size_t)b * CH * HW + n;
    float s = 0.f, s2 = 0.f;
#pragma unroll 16
    for (int c = 0; c < CH; c++) {
        float v = xb[(size_t)c * HW];
        s += v; s2 += v * v;
    }
    float m   = s * (1.f / CH);
    float var = s2 * (1.f / CH) - m * m;
    mu  [b * HW + n] = m;
    rstd[b * HW + n] = rsqrtf(var + 1e-5f);
}

// ---------------------------------------------------------------------------
// 2) Tiled fp32 GEMM: out[b,oc,n] = sum_k W[oc,k] * load(X[b,k,n])  (+resid)
//    MODE 0: plain   MODE 1: layernorm-on-load   MODE 2: gelu-gate-on-load
//    BM=BN=128, BK=16, 256 threads, 8x8 microtile.
// ---------------------------------------------------------------------------
#define BM 128
#define BN 128
#define BK 16

__device__ __forceinline__ float gelu_exact(float v)
{
    return 0.5f * v * (1.f + erff(v * 0.70710678118654752440f));
}

template <int MODE, bool RESID>
__global__ __launch_bounds__(256) void gemm_k(
    const float* __restrict__ W,      // (OC, K) row-major
    const float* __restrict__ X,      // (B, XCH, HW)
    const float* __restrict__ mu,
    const float* __restrict__ rstd,
    const float* __restrict__ lnw,
    const float* __restrict__ lnb,
    const float* __restrict__ resid,  // (B, OC, HW) when RESID
    float* __restrict__ out,          // (B, OC, HW)
    int OC, int K, int XCH)
{
    __shared__ float Ws[BM * BK];
    __shared__ float Xs[BK * BN];

    const int b   = blockIdx.z;
    const int n0  = blockIdx.x * BN;
    const int oc0 = blockIdx.y * BM;
    const int tid = threadIdx.x;
    const int tx  = tid & 15;        // n micro-group
    const int ty  = tid >> 4;        // oc micro-group

    const float* Xb = X + (size_t)b * XCH * HW;

    float acc[8][8];
#pragma unroll
    for (int u = 0; u < 8; u++)
#pragma unroll
        for (int v = 0; v < 8; v++) acc[u][v] = 0.f;

    for (int k0 = 0; k0 < K; k0 += BK) {
        // --- load W tile (BM x BK) ---
#pragma unroll
        for (int i = 0; i < 8; i++) {
            int idx = tid + i * 256;
            int r = idx >> 4, c = idx & 15;
            Ws[idx] = W[(size_t)(oc0 + r) * K + (k0 + c)];
        }
        // --- load X tile (BK x BN) with optional transform ---
#pragma unroll
        for (int i = 0; i < 8; i++) {
            int idx  = tid + i * 256;
            int kk   = idx >> 7;
            int col  = idx & 127;
            int kg   = k0 + kk;
            int n    = n0 + col;
            float v;
            if (MODE == 0) {
                v = Xb[(size_t)kg * HW + n];
            } else if (MODE == 1) {
                float xv = Xb[(size_t)kg * HW + n];
                int bn = b * HW + n;
                v = (xv - mu[bn]) * rstd[bn] * lnw[kg] + lnb[kg];
            } else {
                float v1 = Xb[(size_t)kg * HW + n];
                float v2 = Xb[(size_t)(kg + 256) * HW + n];
                v = gelu_exact(v1) * v2;
            }
            Xs[idx] = v;
        }
        __syncthreads();

#pragma unroll
        for (int k = 0; k < BK; k++) {
            float a[8], bb[8];
#pragma unroll
            for (int u = 0; u < 8; u++) a[u]  = Ws[(ty * 8 + u) * BK + k];
#pragma unroll
            for (int v = 0; v < 8; v++) bb[v] = Xs[k * BN + tx * 8 + v];
#pragma unroll
            for (int u = 0; u < 8; u++)
#pragma unroll
                for (int v = 0; v < 8; v++)
                    acc[u][v] = fmaf(a[u], bb[v], acc[u][v]);
        }
        __syncthreads();
    }

#pragma unroll
    for (int u = 0; u < 8; u++) {
        int oc = oc0 + ty * 8 + u;
        size_t base = ((size_t)b * OC + oc) * HW + n0 + tx * 8;
#pragma unroll
        for (int v = 0; v < 8; v++) {
            float r = acc[u][v];
            if (RESID) r += resid[base + v];
            out[base + v] = r;
        }
    }
}

// ---------------------------------------------------------------------------
// 3) Depthwise 3x3 conv, SAME padding, per-plane shared tile
//    grid: (W/32, H/8, B*CHN), block (32,8)
// ---------------------------------------------------------------------------
__global__ __launch_bounds__(256) void dwconv_k(const float* __restrict__ in,
                                                const float* __restrict__ wd,
                                                float* __restrict__ out,
                                                int CHN)
{
    __shared__ float t[10][34];
    int plane = blockIdx.z;            // b*CHN + ch
    int ch    = plane % CHN;
    size_t base = (size_t)plane * HW;

    int x0 = blockIdx.x * 32;
    int y0 = blockIdx.y * 8;
    int tid = threadIdx.y * 32 + threadIdx.x;

    for (int idx = tid; idx < 340; idx += 256) {
        int r = idx / 34, c = idx % 34;
        int gy = y0 - 1 + r, gx = x0 - 1 + c;
        float v = 0.f;
        if (gy >= 0 && gy < 128 && gx >= 0 && gx < 128)
            v = in[base + gy * 128 + gx];
        t[r][c] = v;
    }
    __syncthreads();

    float w0 = wd[ch * 9 + 0], w1 = wd[ch * 9 + 1], w2 = wd[ch * 9 + 2];
    float w3 = wd[ch * 9 + 3], w4 = wd[ch * 9 + 4], w5 = wd[ch * 9 + 5];
    float w6 = wd[ch * 9 + 6], w7 = wd[ch * 9 + 7], w8 = wd[ch * 9 + 8];

    int ty = threadIdx.y, tx = threadIdx.x;
    float acc = t[ty + 0][tx + 0] * w0 + t[ty + 0][tx + 1] * w1 + t[ty + 0][tx + 2] * w2
              + t[ty + 1][tx + 0] * w3 + t[ty + 1][tx + 1] * w4 + t[ty + 1][tx + 2] * w5
              + t[ty + 2][tx + 0] * w6 + t[ty + 2][tx + 1] * w7 + t[ty + 2][tx + 2] * w8;
    out[base + (y0 + ty) * 128 + (x0 + tx)] = acc;
}

// ---------------------------------------------------------------------------
// 4) Attention logits, split-K over n. grid (8 segs, 32 bh), 256 threads.
//    Also accumulates ||q_i||^2 and ||k_j||^2 (fused l2norm reduction).
// ---------------------------------------------------------------------------
__global__ __launch_bounds__(256) void attn_logits_k(const float* __restrict__ qkv)
{
    int seg = blockIdx.x;              // 0..7 : n-chunk of 2048
    int bh  = blockIdx.y;              // 0..31
    int b = bh >> 3, h = bh & 7;
    const float* qb = qkv + ((size_t)b * 384 + h * DHEAD) * HW;
    const float* kb = qkv + ((size_t)b * 384 + 128 + h * DHEAD) * HW;

    int warp = threadIdx.x >> 5, lane = threadIdx.x & 31;
    int jhalf  = warp & 1;             // j in [jhalf*8, jhalf*8+8)
    int stripe = warp >> 1;            // 4 stripes of 512 n

    float acc[16][8];
#pragma unroll
    for (int i = 0; i < 16; i++)
#pragma unroll
        for (int j = 0; j < 8; j++) acc[i][j] = 0.f;
    float qss[16]; float kss[8];
#pragma unroll
    for (int i = 0; i < 16; i++) qss[i] = 0.f;
#pragma unroll
    for (int j = 0; j < 8; j++)  kss[j] = 0.f;

    int nbase = seg * 2048 + stripe * 512 + lane;
    for (int it = 0; it < 16; it++) {
        int n = nbase + it * 32;
        float qv[16], kv[8];
#pragma unroll
        for (int i = 0; i < 16; i++) qv[i] = qb[(size_t)i * HW + n];
#pragma unroll
        for (int j = 0; j < 8; j++)  kv[j] = kb[(size_t)(jhalf * 8 + j) * HW + n];
#pragma unroll
        for (int i = 0; i < 16; i++) qss[i] = fmaf(qv[i], qv[i], qss[i]);
#pragma unroll
        for (int j = 0; j < 8; j++)  kss[j] = fmaf(kv[j], kv[j], kss[j]);
#pragma unroll
        for (int i = 0; i < 16; i++)
#pragma unroll
            for (int j = 0; j < 8; j++)
                acc[i][j] = fmaf(qv[i], kv[j], acc[i][j]);
    }

    __shared__ float S[256];
    __shared__ float Q2[16], K2[16];
    S[threadIdx.x] = 0.f;
    if (threadIdx.x < 16) { Q2[threadIdx.x] = 0.f; K2[threadIdx.x] = 0.f; }
    __syncthreads();

#pragma unroll
    for (int i = 0; i < 16; i++) {
#pragma unroll
        for (int j = 0; j < 8; j++) {
            float v = acc[i][j];
            v += __shfl_xor_sync(0xffffffffu, v, 16);
            v += __shfl_xor_sync(0xffffffffu, v, 8);
            v += __shfl_xor_sync(0xffffffffu, v, 4);
            v += __shfl_xor_sync(0xffffffffu, v, 2);
            v += __shfl_xor_sync(0xffffffffu, v, 1);
            if (lane == 0) atomicAdd(&S[i * 16 + jhalf * 8 + j], v);
        }
        float q = qss[i];
        q += __shfl_xor_sync(0xffffffffu, q, 16);
        q += __shfl_xor_sync(0xffffffffu, q, 8);
        q += __shfl_xor_sync(0xffffffffu, q, 4);
        q += __shfl_xor_sync(0xffffffffu, q, 2);
        q += __shfl_xor_sync(0xffffffffu, q, 1);
        if (lane == 0 && jhalf == 0) atomicAdd(&Q2[i], q);
    }
#pragma unroll
    for (int j = 0; j < 8; j++) {
        float kq = kss[j];
        kq += __shfl_xor_sync(0xffffffffu, kq, 16);
        kq += __shfl_xor_sync(0xffffffffu, kq, 8);
        kq += __shfl_xor_sync(0xffffffffu, kq, 4);
        kq += __shfl_xor_sync(0xffffffffu, kq, 2);
        kq += __shfl_xor_sync(0xffffffffu, kq, 1);
        if (lane == 0) atomicAdd(&K2[jhalf * 8 + j], kq);
    }
    __syncthreads();

    int slot = bh * 8 + seg;
    g_partS[slot * 256 + threadIdx.x] = S[threadIdx.x];
    if (threadIdx.x < 16) {
        g_partQ2[slot * 16 + threadIdx.x] = Q2[threadIdx.x];
        g_partK2[slot * 16 + threadIdx.x] = K2[threadIdx.x];
    }
}

// ---------------------------------------------------------------------------
// 5) Finalize attention: reduce segments, l2norm scale, temperature, softmax.
//    grid 32 blocks, 256 threads (thread = (i,j) entry).
// ---------------------------------------------------------------------------
__global__ __launch_bounds__(256) void attn_finalize_k(const float* __restrict__ temp)
{
    int bh = blockIdx.x;
    int h = bh & 7;
    int i = threadIdx.x >> 4, j = threadIdx.x & 15;

    float s = 0.f, q2 = 0.f, k2 = 0.f;
#pragma unroll
    for (int seg = 0; seg < 8; seg++) {
        int slot = bh * 8 + seg;
        s  += g_partS [slot * 256 + threadIdx.x];
        q2 += g_partQ2[slot * 16 + i];
        k2 += g_partK2[slot * 16 + j];
    }
    float rq = 1.f / fmaxf(sqrtf(q2), 1e-12f);
    float rk = 1.f / fmaxf(sqrtf(k2), 1e-12f);
    s = s * rq * rk * temp[h];

    // softmax across j (groups of 16 lanes)
    float m = s;
    m = fmaxf(m, __shfl_xor_sync(0xffffffffu, m, 8, 16));
    m = fmaxf(m, __shfl_xor_sync(0xffffffffu, m, 4, 16));
    m = fmaxf(m, __shfl_xor_sync(0xffffffffu, m, 2, 16));
    m = fmaxf(m, __shfl_xor_sync(0xffffffffu, m, 1, 16));
    float e = expf(s - m);
    float sum = e;
    sum += __shfl_xor_sync(0xffffffffu, sum, 8, 16);
    sum += __shfl_xor_sync(0xffffffffu, sum, 4, 16);
    sum += __shfl_xor_sync(0xffffffffu, sum, 2, 16);
    sum += __shfl_xor_sync(0xffffffffu, sum, 1, 16);
    g_attn[bh * 256 + threadIdx.x] = e / sum;
}

// ---------------------------------------------------------------------------
// 6) Apply attention: out[b, h*16+i, n] = sum_e attn[i,e] * v[b, h*16+e, n]
//    grid (HW/256, 32), 256 threads (thread = one n)
// ---------------------------------------------------------------------------
__global__ __launch_bounds__(256) void attn_apply_k(const float* __restrict__ qkv,
                                                    float* __restrict__ out)
{
    int bh = blockIdx.y;
    int b = bh >> 3, h = bh & 7;
    const float* vb = qkv + ((size_t)b * 384 + 256 + h * DHEAD) * HW;
    float* ob = out + ((size_t)b * CH + h * DHEAD) * HW;

    __shared__ float A[256];
    A[threadIdx.x] = g_attn[bh * 256 + threadIdx.x];
    __syncthreads();

    int n = blockIdx.x * 256 + threadIdx.x;
    float vv[16];
#pragma unroll
    for (int e = 0; e < 16; e++) vv[e] = vb[(size_t)e * HW + n];
#pragma unroll
    for (int i = 0; i < 16; i++) {
        float s = 0.f;
#pragma unroll
        for (int e = 0; e < 16; e++) s = fmaf(A[i * 16 + e], vv[e], s);
        ob[(size_t)i * HW + n] = s;
    }
}

// ---------------------------------------------------------------------------
// Launch
// ---------------------------------------------------------------------------
extern "C" void kernel_launch(void* const* d_in, const int* in_sizes, int n_in,
                              void* d_out, int out_size)
{
    const float* x      = (const float*)d_in[0];
    const float* ln1_w  = (const float*)d_in[1];
    const float* ln1_b  = (const float*)d_in[2];
    const float* temp   = (const float*)d_in[3];
    const float* qkv_pw = (const float*)d_in[4];
    const float* qkv_dw = (const float*)d_in[5];
    const float* proj_w = (const float*)d_in[6];
    const float* ln2_w  = (const float*)d_in[7];
    const float* ln2_b  = (const float*)d_in[8];
    const float* g1_w   = (const float*)d_in[9];
    const float* gd_w   = (const float*)d_in[10];
    const float* g2_w   = (const float*)d_in[11];
    float* out = (float*)d_out;

    float *bufA, *bufB, *obuf, *mu, *rstd;
    cudaGetSymbolAddress((void**)&bufA, g_bufA);
    cudaGetSymbolAddress((void**)&bufB, g_bufB);
    cudaGetSymbolAddress((void**)&obuf, g_out);
    cudaGetSymbolAddress((void**)&mu,   g_mu);
    cudaGetSymbolAddress((void**)&rstd, g_rstd);

    dim3 b256(256);

    // --- MDTA ---
    ln_stats_k<<<dim3(HW / 256, BATCH), b256>>>(x, mu, rstd);
    // qkv = dwconv(pconv(LN(x)))
    gemm_k<1, false><<<dim3(HW / BN, 384 / BM, BATCH), b256>>>(
        qkv_pw, x, mu, rstd, ln1_w, ln1_b, nullptr, bufA, 384, 128, 128);
    dwconv_k<<<dim3(4, 16, BATCH * 384), dim3(32, 8)>>>(bufA, qkv_dw, bufB, 384);
    // channel attention
    attn_logits_k<<<dim3(8, 32), b256>>>(bufB);
    attn_finalize_k<<<32, b256>>>(temp);
    attn_apply_k<<<dim3(HW / 256, 32), b256>>>(bufB, obuf);
    // x2 = x + proj(out)
    gemm_k<0, true><<<dim3(HW / BN, 1, BATCH), b256>>>(
        proj_w, obuf, nullptr, nullptr, nullptr, nullptr, x, out, 128, 128, 128);

    // --- GDFN ---
    ln_stats_k<<<dim3(HW / 256, BATCH), b256>>>(out, mu, rstd);
    gemm_k<1, false><<<dim3(HW / BN, 512 / BM, BATCH), b256>>>(
        g1_w, out, mu, rstd, ln2_w, ln2_b, nullptr, bufA, 512, 128, 128);
    dwconv_k<<<dim3(4, 16, BATCH * 512), dim3(32, 8)>>>(bufA, gd_w, bufB, 512);
    // out = out + g2( gelu(x1)*x2 )
    gemm_k<2, true><<<dim3(HW / BN, 1, BATCH), b256>>>(
        g2_w, bufB, nullptr, nullptr, nullptr, nullptr, out, out, 128, 256, 512);
}

// round 2
// speedup vs baseline: 2.0245x; 2.0245x over previous
#include <cuda_runtime.h>
#include <cuda_bf16.h>
#include <math.h>
#include <stdint.h>

// ---------------------------------------------------------------------------
// Problem constants (B=4, C=128, H=W=128, NH=8, d=16, GDFN hidden=512)
// ---------------------------------------------------------------------------
#define BATCH 4
#define CH    128
#define HW    16384          // 128*128
#define NHEAD 8
#define DHEAD 16

#define ALOG_SEGS 128        // attn logits: 128-pixel segments -> 128 segs

// ---------------------------------------------------------------------------
// Scratch (device globals; no allocation allowed)
// ---------------------------------------------------------------------------
__device__ float g_bufA[BATCH * 512 * HW];   // qkv_pre / g1 output (max 512 ch)
__device__ float g_bufB[BATCH * 512 * HW];   // qkv (post dw) / hdn (post dw)
__device__ float g_out [BATCH * CH  * HW];   // attention output (b,c,hw)
__device__ float g_mu  [BATCH * HW];
__device__ float g_rstd[BATCH * HW];
__device__ float g_partS [32 * ALOG_SEGS * 256];  // partial logits
__device__ float g_partQ2[32 * ALOG_SEGS * 16];
__device__ float g_partK2[32 * ALOG_SEGS * 16];
__device__ float g_attn  [32 * 256];              // softmaxed attn [bh][16*16]

// ---------------------------------------------------------------------------
// helpers
// ---------------------------------------------------------------------------
__device__ __forceinline__ uint32_t f2tf(float v)
{
    uint32_t r;
    asm("cvt.rna.tf32.f32 %0, %1;" : "=r"(r) : "f"(v));
    return r;
}

__device__ __forceinline__ void mma_tf32(float* d, const uint32_t* a, const uint32_t* b)
{
    asm volatile(
        "mma.sync.aligned.m16n8k8.row.col.f32.tf32.tf32.f32 "
        "{%0,%1,%2,%3},{%4,%5,%6,%7},{%8,%9},{%0,%1,%2,%3};"
        : "+f"(d[0]), "+f"(d[1]), "+f"(d[2]), "+f"(d[3])
        : "r"(a[0]), "r"(a[1]), "r"(a[2]), "r"(a[3]), "r"(b[0]), "r"(b[1]));
}

__device__ __forceinline__ float gelu_exact(float v)
{
    return 0.5f * v * (1.f + erff(v * 0.70710678118654752440f));
}

// ---------------------------------------------------------------------------
// 1) Per-pixel LayerNorm stats over C=128 channels
// ---------------------------------------------------------------------------
__global__ __launch_bounds__(256) void ln_stats_k(const float* __restrict__ x,
                                                  float* __restrict__ mu,
                                                  float* __restrict__ rstd)
{
    int b = blockIdx.y;
    int n = blockIdx.x * 256 + threadIdx.x;
    const float* xb = x + (size_t)b * CH * HW + n;
    float s = 0.f, s2 = 0.f;
#pragma unroll 16
    for (int c = 0; c < CH; c++) {
        float v = xb[(size_t)c * HW];
        s += v; s2 += v * v;
    }
    float m   = s * (1.f / CH);
    float var = s2 * (1.f / CH) - m * m;
    mu  [b * HW + n] = m;
    rstd[b * HW + n] = rsqrtf(var + 1e-5f);
}

// ---------------------------------------------------------------------------
// 2) tf32 tensor-core GEMM: out[b,oc,n] = sum_k W[oc,k] * load(X[b,k,n])
//    MODE 0: plain   MODE 1: layernorm-on-load   MODE 2: gelu-gate-on-load
//    Block 128x128, BK=16, 256 threads (8 warps, warp tile 64x32),
//    double-buffered smem, m16n8k8 tf32 MMA, fp32 accumulate.
// ---------------------------------------------------------------------------
#define BM  128
#define BN  128
#define BK  16
#define BKP 20      // padded k-stride for Ws  (conflict-free A loads)
#define BNP 136     // padded n-stride for Xs  (conflict-free B loads)

template <int MODE, bool RESID>
__global__ __launch_bounds__(256) void gemm_tc(
    const float* __restrict__ W,      // (OC, K) row-major
    const float* __restrict__ X,      // (B, XCH, HW)
    const float* __restrict__ mu,
    const float* __restrict__ rstd,
    const float* __restrict__ lnw,
    const float* __restrict__ lnb,
    const float* __restrict__ resid,  // (B, OC, HW) when RESID
    float* __restrict__ out,          // (B, OC, HW)
    int OC, int K, int XCH)
{
    __shared__ uint32_t Ws[2][BM * BKP];
    __shared__ uint32_t Xs[2][BK * BNP];

    const int b    = blockIdx.z;
    const int n0   = blockIdx.x * BN;
    const int oc0  = blockIdx.y * BM;
    const int tid  = threadIdx.x;
    const int warp = tid >> 5;
    const int lane = tid & 31;
    const int wm   = warp >> 2;       // 0..1  (m tile of 64)
    const int wn   = warp & 3;        // 0..3  (n tile of 32)
    const int gid  = lane >> 2;       // 0..7
    const int tig  = lane & 3;        // 0..3

    const float* Xb = X + (size_t)b * XCH * HW;

    float acc[4][4][4];
#pragma unroll
    for (int mt = 0; mt < 4; mt++)
#pragma unroll
        for (int nt = 0; nt < 4; nt++)
#pragma unroll
            for (int r = 0; r < 4; r++) acc[mt][nt][r] = 0.f;

    // loader geometry: 512 float4 per tile, 2 per thread
    const int widx0 = tid, widx1 = tid + 256;          // W: row = idx>>2, c4 = (idx&3)*4
    const int xidx0 = tid, xidx1 = tid + 256;          // X: row = idx>>5, n4 = (idx&31)*4

    float4 wreg[2];
    float4 xreg[2];

    auto load_global = [&](int k0) {
#pragma unroll
        for (int t = 0; t < 2; t++) {
            int idx = t == 0 ? widx0 : widx1;
            int r = idx >> 2, c4 = (idx & 3) << 2;
            wreg[t] = *(const float4*)&W[(size_t)(oc0 + r) * K + k0 + c4];
        }
#pragma unroll
        for (int t = 0; t < 2; t++) {
            int idx = t == 0 ? xidx0 : xidx1;
            int kk = idx >> 5, n4 = (idx & 31) << 2;
            int kg = k0 + kk;
            int n  = n0 + n4;
            if (MODE == 0) {
                xreg[t] = *(const float4*)&Xb[(size_t)kg * HW + n];
            } else if (MODE == 1) {
                float4 xv = *(const float4*)&Xb[(size_t)kg * HW + n];
                float4 m4 = *(const float4*)&mu  [b * HW + n];
                float4 r4 = *(const float4*)&rstd[b * HW + n];
                float wsc = lnw[kg], bsc = lnb[kg];
                xreg[t].x = (xv.x - m4.x) * r4.x * wsc + bsc;
                xreg[t].y = (xv.y - m4.y) * r4.y * wsc + bsc;
                xreg[t].z = (xv.z - m4.z) * r4.z * wsc + bsc;
                xreg[t].w = (xv.w - m4.w) * r4.w * wsc + bsc;
            } else {
                float4 v1 = *(const float4*)&Xb[(size_t)kg * HW + n];
                float4 v2 = *(const float4*)&Xb[(size_t)(kg + 256) * HW + n];
                xreg[t].x = gelu_exact(v1.x) * v2.x;
                xreg[t].y = gelu_exact(v1.y) * v2.y;
                xreg[t].z = gelu_exact(v1.z) * v2.z;
                xreg[t].w = gelu_exact(v1.w) * v2.w;
            }
        }
    };

    auto store_smem = [&](int buf) {
#pragma unroll
        for (int t = 0; t < 2; t++) {
            int idx = t == 0 ? widx0 : widx1;
            int r = idx >> 2, c4 = (idx & 3) << 2;
            uint32_t* p = &Ws[buf][r * BKP + c4];
            p[0] = f2tf(wreg[t].x); p[1] = f2tf(wreg[t].y);
            p[2] = f2tf(wreg[t].z); p[3] = f2tf(wreg[t].w);
        }
#pragma unroll
        for (int t = 0; t < 2; t++) {
            int idx = t == 0 ? xidx0 : xidx1;
            int kk = idx >> 5, n4 = (idx & 31) << 2;
            uint32_t* p = &Xs[buf][kk * BNP + n4];
            p[0] = f2tf(xreg[t].x); p[1] = f2tf(xreg[t].y);
            p[2] = f2tf(xreg[t].z); p[3] = f2tf(xreg[t].w);
        }
    };

    const int nstages = K / BK;
    load_global(0);
    store_smem(0);
    __syncthreads();

    for (int s = 0; s < nstages; s++) {
        int buf = s & 1;
        if (s + 1 < nstages) load_global((s + 1) * BK);

        // compute from smem[buf]: 2 k-steps of 8
#pragma unroll
        for (int ks = 0; ks < 2; ks++) {
            uint32_t afr[4][4], bfr[4][2];
#pragma unroll
            for (int mt = 0; mt < 4; mt++) {
                int r = wm * 64 + mt * 16 + gid;
                int c = ks * 8 + tig;
                afr[mt][0] = Ws[buf][r * BKP + c];
                afr[mt][1] = Ws[buf][(r + 8) * BKP + c];
                afr[mt][2] = Ws[buf][r * BKP + c + 4];
                afr[mt][3] = Ws[buf][(r + 8) * BKP + c + 4];
            }
#pragma unroll
            for (int nt = 0; nt < 4; nt++) {
                int col = wn * 32 + nt * 8 + gid;
                bfr[nt][0] = Xs[buf][(ks * 8 + tig) * BNP + col];
                bfr[nt][1] = Xs[buf][(ks * 8 + tig + 4) * BNP + col];
            }
#pragma unroll
            for (int mt = 0; mt < 4; mt++)
#pragma unroll
                for (int nt = 0; nt < 4; nt++)
                    mma_tf32(acc[mt][nt], afr[mt], bfr[nt]);
        }
        __syncthreads();
        if (s + 1 < nstages) {
            store_smem(buf ^ 1);
            __syncthreads();
        }
    }

    // epilogue: float2 stores (+optional residual)
#pragma unroll
    for (int mt = 0; mt < 4; mt++) {
#pragma unroll
        for (int nt = 0; nt < 4; nt++) {
            int oc = oc0 + wm * 64 + mt * 16 + gid;
            int n  = n0 + wn * 32 + nt * 8 + tig * 2;
            size_t base0 = ((size_t)b * OC + oc) * HW + n;
            size_t base1 = ((size_t)b * OC + oc + 8) * HW + n;
            float2 r0 = make_float2(acc[mt][nt][0], acc[mt][nt][1]);
            float2 r1 = make_float2(acc[mt][nt][2], acc[mt][nt][3]);
            if (RESID) {
                float2 q0 = *(const float2*)&resid[base0];
                float2 q1 = *(const float2*)&resid[base1];
                r0.x += q0.x; r0.y += q0.y;
                r1.x += q1.x; r1.y += q1.y;
            }
            *(float2*)&out[base0] = r0;
            *(float2*)&out[base1] = r1;
        }
    }
}

// ---------------------------------------------------------------------------
// 3) Depthwise 3x3 conv, SAME padding, per-plane shared tile
// ---------------------------------------------------------------------------
__global__ __launch_bounds__(256) void dwconv_k(const float* __restrict__ in,
                                                const float* __restrict__ wd,
                                                float* __restrict__ out,
                                                int CHN)
{
    __shared__ float t[10][34];
    int plane = blockIdx.z;            // b*CHN + ch
    int ch    = plane % CHN;
    size_t base = (size_t)plane * HW;

    int x0 = blockIdx.x * 32;
    int y0 = blockIdx.y * 8;
    int tid = threadIdx.y * 32 + threadIdx.x;

    for (int idx = tid; idx < 340; idx += 256) {
        int r = idx / 34, c = idx % 34;
        int gy = y0 - 1 + r, gx = x0 - 1 + c;
        float v = 0.f;
        if (gy >= 0 && gy < 128 && gx >= 0 && gx < 128)
            v = in[base + gy * 128 + gx];
        t[r][c] = v;
    }
    __syncthreads();

    float w0 = wd[ch * 9 + 0], w1 = wd[ch * 9 + 1], w2 = wd[ch * 9 + 2];
    float w3 = wd[ch * 9 + 3], w4 = wd[ch * 9 + 4], w5 = wd[ch * 9 + 5];
    float w6 = wd[ch * 9 + 6], w7 = wd[ch * 9 + 7], w8 = wd[ch * 9 + 8];

    int ty = threadIdx.y, tx = threadIdx.x;
    float acc = t[ty + 0][tx + 0] * w0 + t[ty + 0][tx + 1] * w1 + t[ty + 0][tx + 2] * w2
              + t[ty + 1][tx + 0] * w3 + t[ty + 1][tx + 1] * w4 + t[ty + 1][tx + 2] * w5
              + t[ty + 2][tx + 0] * w6 + t[ty + 2][tx + 1] * w7 + t[ty + 2][tx + 2] * w8;
    out[base + (y0 + ty) * 128 + (x0 + tx)] = acc;
}

// ---------------------------------------------------------------------------
// 4) Attention logits, smem-staged. grid (128 segs, 32 bh), 256 threads.
//    thread = (i,j); diagonal threads fuse ||q||^2 / ||k||^2 reduction.
// ---------------------------------------------------------------------------
__global__ __launch_bounds__(256) void attn_logits_k(const float* __restrict__ qkv)
{
    int seg = blockIdx.x;              // 0..127 : 128-pixel chunk
    int bh  = blockIdx.y;              // 0..31
    int b = bh >> 3, h = bh & 7;
    const float* qb = qkv + ((size_t)b * 384 + h * DHEAD) * HW + seg * 128;
    const float* kb = qkv + ((size_t)b * 384 + 128 + h * DHEAD) * HW + seg * 128;

    __shared__ float qs[16][132];      // row-padded: broadcast-friendly
    __shared__ float kt[128][17];      // transposed: conflict-free j reads

    int tid = threadIdx.x;
#pragma unroll
    for (int t = 0; t < 8; t++) {
        int idx = tid + t * 256;
        int row = idx >> 7, n = idx & 127;
        qs[row][n] = qb[(size_t)row * HW + n];
        kt[n][row] = kb[(size_t)row * HW + n];
    }
    __syncthreads();

    int i = tid >> 4, j = tid & 15;
    bool diag = (i == j);
    float acc = 0.f, q2 = 0.f, k2 = 0.f;
#pragma unroll 4
    for (int n = 0; n < 128; n++) {
        float qv = qs[i][n];
        float kv = kt[n][j];
        acc = fmaf(qv, kv, acc);
        if (diag) { q2 = fmaf(qv, qv, q2); k2 = fmaf(kv, kv, k2); }
    }

    int slot = bh * ALOG_SEGS + seg;
    g_partS[(size_t)slot * 256 + tid] = acc;
    if (diag) {
        g_partQ2[slot * 16 + i] = q2;
        g_partK2[slot * 16 + i] = k2;
    }
}

// ---------------------------------------------------------------------------
// 5) Finalize: reduce segments, l2norm scale, temperature, softmax.
// ---------------------------------------------------------------------------
__global__ __launch_bounds__(256) void attn_finalize_k(const float* __restrict__ temp)
{
    int bh = blockIdx.x;
    int h = bh & 7;
    int i = threadIdx.x >> 4, j = threadIdx.x & 15;

    float s = 0.f, q2 = 0.f, k2 = 0.f;
    for (int seg = 0; seg < ALOG_SEGS; seg++) {
        int slot = bh * ALOG_SEGS + seg;
        s  += g_partS [(size_t)slot * 256 + threadIdx.x];
        q2 += g_partQ2[slot * 16 + i];
        k2 += g_partK2[slot * 16 + j];
    }
    float rq = 1.f / fmaxf(sqrtf(q2), 1e-12f);
    float rk = 1.f / fmaxf(sqrtf(k2), 1e-12f);
    s = s * rq * rk * temp[h];

    float m = s;
    m = fmaxf(m, __shfl_xor_sync(0xffffffffu, m, 8, 16));
    m = fmaxf(m, __shfl_xor_sync(0xffffffffu, m, 4, 16));
    m = fmaxf(m, __shfl_xor_sync(0xffffffffu, m, 2, 16));
    m = fmaxf(m, __shfl_xor_sync(0xffffffffu, m, 1, 16));
    float e = expf(s - m);
    float sum = e;
    sum += __shfl_xor_sync(0xffffffffu, sum, 8, 16);
    sum += __shfl_xor_sync(0xffffffffu, sum, 4, 16);
    sum += __shfl_xor_sync(0xffffffffu, sum, 2, 16);
    sum += __shfl_xor_sync(0xffffffffu, sum, 1, 16);
    g_attn[bh * 256 + threadIdx.x] = e / sum;
}

// ---------------------------------------------------------------------------
// 6) Apply attention: out[b, h*16+i, n] = sum_e attn[i,e] * v[b, h*16+e, n]
// ---------------------------------------------------------------------------
__global__ __launch_bounds__(256) void attn_apply_k(const float* __restrict__ qkv,
                                                    float* __restrict__ out)
{
    int bh = blockIdx.y;
    int b = bh >> 3, h = bh & 7;
    const float* vb = qkv + ((size_t)b * 384 + 256 + h * DHEAD) * HW;
    float* ob = out + ((size_t)b * CH + h * DHEAD) * HW;

    __shared__ float A[256];
    A[threadIdx.x] = g_attn[bh * 256 + threadIdx.x];
    __syncthreads();

    int n = blockIdx.x * 256 + threadIdx.x;
    float vv[16];
#pragma unroll
    for (int e = 0; e < 16; e++) vv[e] = vb[(size_t)e * HW + n];
#pragma unroll
    for (int i = 0; i < 16; i++) {
        float s = 0.f;
#pragma unroll
        for (int e = 0; e < 16; e++) s = fmaf(A[i * 16 + e], vv[e], s);
        ob[(size_t)i * HW + n] = s;
    }
}

// ---------------------------------------------------------------------------
// Launch
// ---------------------------------------------------------------------------
extern "C" void kernel_launch(void* const* d_in, const int* in_sizes, int n_in,
                              void* d_out, int out_size)
{
    const float* x      = (const float*)d_in[0];
    const float* ln1_w  = (const float*)d_in[1];
    const float* ln1_b  = (const float*)d_in[2];
    const float* temp   = (const float*)d_in[3];
    const float* qkv_pw = (const float*)d_in[4];
    const float* qkv_dw = (const float*)d_in[5];
    const float* proj_w = (const float*)d_in[6];
    const float* ln2_w  = (const float*)d_in[7];
    const float* ln2_b  = (const float*)d_in[8];
    const float* g1_w   = (const float*)d_in[9];
    const float* gd_w   = (const float*)d_in[10];
    const float* g2_w   = (const float*)d_in[11];
    float* out = (float*)d_out;

    float *bufA, *bufB, *obuf, *mu, *rstd;
    cudaGetSymbolAddress((void**)&bufA, g_bufA);
    cudaGetSymbolAddress((void**)&bufB, g_bufB);
    cudaGetSymbolAddress((void**)&obuf, g_out);
    cudaGetSymbolAddress((void**)&mu,   g_mu);
    cudaGetSymbolAddress((void**)&rstd, g_rstd);

    dim3 b256(256);

    // --- MDTA ---
    ln_stats_k<<<dim3(HW / 256, BATCH), b256>>>(x, mu, rstd);
    gemm_tc<1, false><<<dim3(HW / BN, 384 / BM, BATCH), b256>>>(
        qkv_pw, x, mu, rstd, ln1_w, ln1_b, nullptr, bufA, 384, 128, 128);
    dwconv_k<<<dim3(4, 16, BATCH * 384), dim3(32, 8)>>>(bufA, qkv_dw, bufB, 384);
    attn_logits_k<<<dim3(ALOG_SEGS, 32), b256>>>(bufB);
    attn_finalize_k<<<32, b256>>>(temp);
    attn_apply_k<<<dim3(HW / 256, 32), b256>>>(bufB, obuf);
    gemm_tc<0, true><<<dim3(HW / BN, 1, BATCH), b256>>>(
        proj_w, obuf, nullptr, nullptr, nullptr, nullptr, x, out, 128, 128, 128);

    // --- GDFN ---
    ln_stats_k<<<dim3(HW / 256, BATCH), b256>>>(out, mu, rstd);
    gemm_tc<1, false><<<dim3(HW / BN, 512 / BM, BATCH), b256>>>(
        g1_w, out, mu, rstd, ln2_w, ln2_b, nullptr, bufA, 512, 128, 128);
    dwconv_k<<<dim3(4, 16, BATCH * 512), dim3(32, 8)>>>(bufA, gd_w, bufB, 512);
    gemm_tc<2, true><<<dim3(HW / BN, 1, BATCH), b256>>>(
        g2_w, bufB, nullptr, nullptr, nullptr, nullptr, out, out, 128, 256, 512);
}

// round 3
// speedup vs baseline: 2.1079x; 1.0412x over previous
#include <cuda_runtime.h>
#include <cuda_bf16.h>
#include <math.h>
#include <stdint.h>

// ---------------------------------------------------------------------------
// Problem constants (B=4, C=128, H=W=128, NH=8, d=16, GDFN hidden=512)
// ---------------------------------------------------------------------------
#define BATCH 4
#define CH    128
#define HW    16384
#define NHEAD 8
#define DHEAD 16
#define ALOG_SEGS 128

// ---------------------------------------------------------------------------
// Scratch (device globals)
// ---------------------------------------------------------------------------
__device__ float g_bufA[BATCH * 512 * HW];
__device__ float g_bufB[BATCH * 512 * HW];
__device__ float g_partS [32 * ALOG_SEGS * 256];
__device__ float g_partQ2[32 * ALOG_SEGS * 16];
__device__ float g_partK2[32 * ALOG_SEGS * 16];
__device__ float g_attn  [32 * 256];
__device__ float g_WqP [384 * 128];     // qkv weights pre-scaled by ln1_w
__device__ float g_Wg1P[512 * 128];     // g1 weights pre-scaled by ln2_w
__device__ float g_rs  [896];           // rowsums (384 qkv | 512 g1)
__device__ float g_cb  [896];           // const bias terms
__device__ float g_Weff[BATCH * 128 * 128];  // per-batch proj·attn weights

// ---------------------------------------------------------------------------
// helpers
// ---------------------------------------------------------------------------
__device__ __forceinline__ uint32_t f2tf(float v)
{
    uint32_t r;
    asm("cvt.rna.tf32.f32 %0, %1;" : "=r"(r) : "f"(v));
    return r;
}

__device__ __forceinline__ void mma_tf32(float* d, const uint32_t* a, const uint32_t* b)
{
    asm volatile(
        "mma.sync.aligned.m16n8k8.row.col.f32.tf32.tf32.f32 "
        "{%0,%1,%2,%3},{%4,%5,%6,%7},{%8,%9},{%0,%1,%2,%3};"
        : "+f"(d[0]), "+f"(d[1]), "+f"(d[2]), "+f"(d[3])
        : "r"(a[0]), "r"(a[1]), "r"(a[2]), "r"(a[3]), "r"(b[0]), "r"(b[1]));
}

__device__ __forceinline__ float gelu_exact(float v)
{
    return 0.5f * v * (1.f + erff(v * 0.70710678118654752440f));
}

// ---------------------------------------------------------------------------
// 0) Weight prep: W'[o,c] = W[o,c]*lnw[c]; rowsum[o] = sum W'; cb[o] = sum W*lnb
//    One warp per output row. Rows 0..383 -> qkv, 384..895 -> g1.
// ---------------------------------------------------------------------------
__global__ __launch_bounds__(256) void prep_w_k(const float* __restrict__ qkv_pw,
                                                const float* __restrict__ ln1w,
                                                const float* __restrict__ ln1b,
                                                const float* __restrict__ g1w,
                                                const float* __restrict__ ln2w,
                                                const float* __restrict__ ln2b)
{
    int row  = blockIdx.x * 8 + (threadIdx.x >> 5);
    int lane = threadIdx.x & 31;
    const float *W, *lw, *lb;
    float* Wp;
    if (row < 384) { W = qkv_pw + (size_t)row * 128; lw = ln1w; lb = ln1b; Wp = g_WqP + (size_t)row * 128; }
    else           { W = g1w + (size_t)(row - 384) * 128; lw = ln2w; lb = ln2b; Wp = g_Wg1P + (size_t)(row - 384) * 128; }

    float rs = 0.f, cb = 0.f;
#pragma unroll
    for (int t = 0; t < 4; t++) {
        int c = lane + t * 32;
        float w = W[c];
        float wp = w * lw[c];
        Wp[c] = wp;
        rs += wp;
        cb += w * lb[c];
    }
#pragma unroll
    for (int o = 16; o > 0; o >>= 1) {
        rs += __shfl_xor_sync(0xffffffffu, rs, o);
        cb += __shfl_xor_sync(0xffffffffu, cb, o);
    }
    if (lane == 0) { g_rs[row] = rs; g_cb[row] = cb; }
}

// ---------------------------------------------------------------------------
// 1) tf32 tensor-core GEMM, 128x128x16 tiles, 256 threads, double-buffered.
//    MODE 0: plain    MODE 1: LN-in-epilogue (stats computed in-kernel)
//    MODE 2: gelu-gate-on-load
// ---------------------------------------------------------------------------
#define BM  128
#define BN  128
#define BK  16
#define BKP 20
#define BNP 136

template <int MODE, bool RESID>
__global__ __launch_bounds__(256) void gemm_tc(
    const float* __restrict__ W,      // (OC, K) row-major (or per-batch with wbstride)
    const float* __restrict__ X,      // (B, XCH, HW)
    const float* __restrict__ rsum,   // MODE 1: per-row sums of W'
    const float* __restrict__ cbias,  // MODE 1: per-row const bias
    const float* __restrict__ resid,
    float* __restrict__ out,          // (B, OC, HW)
    int OC, int K, int XCH, int wbstride)
{
    __shared__ uint32_t Ws[2][BM * BKP];
    __shared__ uint32_t Xs[2][BK * BNP];

    const int b    = blockIdx.z;
    const int n0   = blockIdx.x * BN;
    const int oc0  = blockIdx.y * BM;
    const int tid  = threadIdx.x;
    const int warp = tid >> 5;
    const int lane = tid & 31;
    const int wm   = warp >> 2;
    const int wn   = warp & 3;
    const int gid  = lane >> 2;
    const int tig  = lane & 3;

    const float* Wb = W + (size_t)b * wbstride;
    const float* Xb = X + (size_t)b * XCH * HW;

    float acc[4][4][4];
#pragma unroll
    for (int mt = 0; mt < 4; mt++)
#pragma unroll
        for (int nt = 0; nt < 4; nt++)
#pragma unroll
            for (int r = 0; r < 4; r++) acc[mt][nt][r] = 0.f;

    // per-thread LN stats (4 fixed columns, 2 k-rows per tile)
    float cs[4]  = {0.f, 0.f, 0.f, 0.f};
    float cs2[4] = {0.f, 0.f, 0.f, 0.f};

    float4 wreg[2], xreg[2];

    auto load_global = [&](int k0) {
#pragma unroll
        for (int t = 0; t < 2; t++) {
            int idx = tid + t * 256;
            int r = idx >> 2, c4 = (idx & 3) << 2;
            wreg[t] = *(const float4*)&Wb[(size_t)(oc0 + r) * K + k0 + c4];
        }
#pragma unroll
        for (int t = 0; t < 2; t++) {
            int idx = tid + t * 256;
            int kk = idx >> 5, n4 = (idx & 31) << 2;
            int kg = k0 + kk;
            int n  = n0 + n4;
            if (MODE == 2) {
                float4 v1 = *(const float4*)&Xb[(size_t)kg * HW + n];
                float4 v2 = *(const float4*)&Xb[(size_t)(kg + 256) * HW + n];
                xreg[t].x = gelu_exact(v1.x) * v2.x;
                xreg[t].y = gelu_exact(v1.y) * v2.y;
                xreg[t].z = gelu_exact(v1.z) * v2.z;
                xreg[t].w = gelu_exact(v1.w) * v2.w;
            } else {
                xreg[t] = *(const float4*)&Xb[(size_t)kg * HW + n];
                if (MODE == 1) {
                    cs[0] += xreg[t].x; cs2[0] = fmaf(xreg[t].x, xreg[t].x, cs2[0]);
                    cs[1] += xreg[t].y; cs2[1] = fmaf(xreg[t].y, xreg[t].y, cs2[1]);
                    cs[2] += xreg[t].z; cs2[2] = fmaf(xreg[t].z, xreg[t].z, cs2[2]);
                    cs[3] += xreg[t].w; cs2[3] = fmaf(xreg[t].w, xreg[t].w, cs2[3]);
                }
            }
        }
    };

    auto store_smem = [&](int buf) {
#pragma unroll
        for (int t = 0; t < 2; t++) {
            int idx = tid + t * 256;
            int r = idx >> 2, c4 = (idx & 3) << 2;
            uint32_t* p = &Ws[buf][r * BKP + c4];
            p[0] = f2tf(wreg[t].x); p[1] = f2tf(wreg[t].y);
            p[2] = f2tf(wreg[t].z); p[3] = f2tf(wreg[t].w);
        }
#pragma unroll
        for (int t = 0; t < 2; t++) {
            int idx = tid + t * 256;
            int kk = idx >> 5, n4 = (idx & 31) << 2;
            uint32_t* p = &Xs[buf][kk * BNP + n4];
            p[0] = f2tf(xreg[t].x); p[1] = f2tf(xreg[t].y);
            p[2] = f2tf(xreg[t].z); p[3] = f2tf(xreg[t].w);
        }
    };

    const int nstages = K / BK;
    load_global(0);
    store_smem(0);
    __syncthreads();

    for (int s = 0; s < nstages; s++) {
        int buf = s & 1;
        if (s + 1 < nstages) load_global((s + 1) * BK);

#pragma unroll
        for (int ks = 0; ks < 2; ks++) {
            uint32_t afr[4][4], bfr[4][2];
#pragma unroll
            for (int mt = 0; mt < 4; mt++) {
                int r = wm * 64 + mt * 16 + gid;
                int c = ks * 8 + tig;
                afr[mt][0] = Ws[buf][r * BKP + c];
                afr[mt][1] = Ws[buf][(r + 8) * BKP + c];
                afr[mt][2] = Ws[buf][r * BKP + c + 4];
                afr[mt][3] = Ws[buf][(r + 8) * BKP + c + 4];
            }
#pragma unroll
            for (int nt = 0; nt < 4; nt++) {
                int col = wn * 32 + nt * 8 + gid;
                bfr[nt][0] = Xs[buf][(ks * 8 + tig) * BNP + col];
                bfr[nt][1] = Xs[buf][(ks * 8 + tig + 4) * BNP + col];
            }
#pragma unroll
            for (int mt = 0; mt < 4; mt++)
#pragma unroll
                for (int nt = 0; nt < 4; nt++)
                    mma_tf32(acc[mt][nt], afr[mt], bfr[nt]);
        }
        __syncthreads();
        if (s + 1 < nstages) {
            store_smem(buf ^ 1);
            __syncthreads();
        }
    }

    // --- MODE 1: reduce per-column stats (overlay dead smem buffers) ---
    float* muS = (float*)&Xs[0][0];          // [128]
    float* rsS = muS + 128;                  // [128]
    if (MODE == 1) {
        float* redS  = (float*)&Ws[0][0];    // [8][128]
        float* redS2 = redS + 8 * 128;       // [8][128]  (fits in Ws[0]: 10240B >= 8192B)
        int jrow = tid >> 5;                 // 0..7
        int nc   = (tid & 31) << 2;
#pragma unroll
        for (int c = 0; c < 4; c++) {
            redS [jrow * 128 + nc + c] = cs[c];
            redS2[jrow * 128 + nc + c] = cs2[c];
        }
        __syncthreads();
        if (tid < 128) {
            float s = 0.f, s2 = 0.f;
#pragma unroll
            for (int j = 0; j < 8; j++) {
                s  += redS [j * 128 + tid];
                s2 += redS2[j * 128 + tid];
            }
            float m   = s * (1.f / 128.f);
            float var = s2 * (1.f / 128.f) - m * m;
            muS[tid] = m;
            rsS[tid] = rsqrtf(var + 1e-5f);
        }
        __syncthreads();
    }

    // --- epilogue ---
#pragma unroll
    for (int mt = 0; mt < 4; mt++) {
        int ocl0 = wm * 64 + mt * 16 + gid;
        float rs0 = 0.f, rs1 = 0.f, cb0 = 0.f, cb1 = 0.f;
        if (MODE == 1) {
            rs0 = rsum[oc0 + ocl0];     rs1 = rsum[oc0 + ocl0 + 8];
            cb0 = cbias[oc0 + ocl0];    cb1 = cbias[oc0 + ocl0 + 8];
        }
#pragma unroll
        for (int nt = 0; nt < 4; nt++) {
            int nl = wn * 32 + nt * 8 + tig * 2;
            size_t base0 = ((size_t)b * OC + oc0 + ocl0) * HW + n0 + nl;
            size_t base1 = ((size_t)b * OC + oc0 + ocl0 + 8) * HW + n0 + nl;
            float2 r0 = make_float2(acc[mt][nt][0], acc[mt][nt][1]);
            float2 r1 = make_float2(acc[mt][nt][2], acc[mt][nt][3]);
            if (MODE == 1) {
                float mu0 = muS[nl], mu1 = muS[nl + 1];
                float rd0 = rsS[nl], rd1 = rsS[nl + 1];
                r0.x = rd0 * (r0.x - mu0 * rs0) + cb0;
                r0.y = rd1 * (r0.y - mu1 * rs0) + cb0;
                r1.x = rd0 * (r1.x - mu0 * rs1) + cb1;
                r1.y = rd1 * (r1.y - mu1 * rs1) + cb1;
            }
            if (RESID) {
                float2 q0 = *(const float2*)&resid[base0];
                float2 q1 = *(const float2*)&resid[base1];
                r0.x += q0.x; r0.y += q0.y;
                r1.x += q1.x; r1.y += q1.y;
            }
            *(float2*)&out[base0] = r0;
            *(float2*)&out[base1] = r1;
        }
    }
}

// ---------------------------------------------------------------------------
// 2) Depthwise 3x3 conv, SAME padding
// ---------------------------------------------------------------------------
__global__ __launch_bounds__(256) void dwconv_k(const float* __restrict__ in,
                                                const float* __restrict__ wd,
                                                float* __restrict__ out,
                                                int CHN)
{
    __shared__ float t[10][34];
    int plane = blockIdx.z;
    int ch    = plane % CHN;
    size_t base = (size_t)plane * HW;

    int x0 = blockIdx.x * 32;
    int y0 = blockIdx.y * 8;
    int tid = threadIdx.y * 32 + threadIdx.x;

    for (int idx = tid; idx < 340; idx += 256) {
        int r = idx / 34, c = idx % 34;
        int gy = y0 - 1 + r, gx = x0 - 1 + c;
        float v = 0.f;
        if (gy >= 0 && gy < 128 && gx >= 0 && gx < 128)
            v = in[base + gy * 128 + gx];
        t[r][c] = v;
    }
    __syncthreads();

    float w0 = wd[ch * 9 + 0], w1 = wd[ch * 9 + 1], w2 = wd[ch * 9 + 2];
    float w3 = wd[ch * 9 + 3], w4 = wd[ch * 9 + 4], w5 = wd[ch * 9 + 5];
    float w6 = wd[ch * 9 + 6], w7 = wd[ch * 9 + 7], w8 = wd[ch * 9 + 8];

    int ty = threadIdx.y, tx = threadIdx.x;
    float acc = t[ty + 0][tx + 0] * w0 + t[ty + 0][tx + 1] * w1 + t[ty + 0][tx + 2] * w2
              + t[ty + 1][tx + 0] * w3 + t[ty + 1][tx + 1] * w4 + t[ty + 1][tx + 2] * w5
              + t[ty + 2][tx + 0] * w6 + t[ty + 2][tx + 1] * w7 + t[ty + 2][tx + 2] * w8;
    out[base + (y0 + ty) * 128 + (x0 + tx)] = acc;
}

// ---------------------------------------------------------------------------
// 3) Attention logits, float4 vectorized. grid (128 segs, 32 bh), 256 threads.
// ---------------------------------------------------------------------------
__global__ __launch_bounds__(256) void attn_logits_k(const float* __restrict__ qkv)
{
    int seg = blockIdx.x;
    int bh  = blockIdx.y;
    int b = bh >> 3, h = bh & 7;
    const float* qb = qkv + ((size_t)b * 384 + h * DHEAD) * HW + seg * 128;
    const float* kb = qkv + ((size_t)b * 384 + 128 + h * DHEAD) * HW + seg * 128;

    __shared__ __align__(16) float qs[16][132];
    __shared__ __align__(16) float ks[16][132];

    int tid = threadIdx.x;
#pragma unroll
    for (int t = 0; t < 8; t++) {
        int idx = tid + t * 256;
        int row = idx >> 7, n = idx & 127;
        qs[row][n] = qb[(size_t)row * HW + n];
        ks[row][n] = kb[(size_t)row * HW + n];
    }
    __syncthreads();

    int i = tid >> 4, j = tid & 15;
    bool diag = (i == j);
    const float4* q4 = (const float4*)&qs[i][0];
    const float4* k4 = (const float4*)&ks[j][0];
    float acc = 0.f, q2 = 0.f, k2 = 0.f;
#pragma unroll 8
    for (int n4 = 0; n4 < 32; n4++) {
        float4 a = q4[n4];
        float4 c = k4[n4];
        acc = fmaf(a.x, c.x, acc); acc = fmaf(a.y, c.y, acc);
        acc = fmaf(a.z, c.z, acc); acc = fmaf(a.w, c.w, acc);
        if (diag) {
            q2 = fmaf(a.x, a.x, q2); q2 = fmaf(a.y, a.y, q2);
            q2 = fmaf(a.z, a.z, q2); q2 = fmaf(a.w, a.w, q2);
            k2 = fmaf(c.x, c.x, k2); k2 = fmaf(c.y, c.y, k2);
            k2 = fmaf(c.z, c.z, k2); k2 = fmaf(c.w, c.w, k2);
        }
    }

    int slot = bh * ALOG_SEGS + seg;
    g_partS[(size_t)slot * 256 + tid] = acc;
    if (diag) {
        g_partQ2[slot * 16 + i] = q2;
        g_partK2[slot * 16 + i] = k2;
    }
}

// ---------------------------------------------------------------------------
// 4) Finalize: reduce segments, l2norm scale, temperature, softmax.
// ---------------------------------------------------------------------------
__global__ __launch_bounds__(256) void attn_finalize_k(const float* __restrict__ temp)
{
    int bh = blockIdx.x;
    int h = bh & 7;
    int i = threadIdx.x >> 4, j = threadIdx.x & 15;

    float s = 0.f, q2 = 0.f, k2 = 0.f;
    for (int seg = 0; seg < ALOG_SEGS; seg++) {
        int slot = bh * ALOG_SEGS + seg;
        s  += g_partS [(size_t)slot * 256 + threadIdx.x];
        q2 += g_partQ2[slot * 16 + i];
        k2 += g_partK2[slot * 16 + j];
    }
    float rq = 1.f / fmaxf(sqrtf(q2), 1e-12f);
    float rk = 1.f / fmaxf(sqrtf(k2), 1e-12f);
    s = s * rq * rk * temp[h];

    float m = s;
    m = fmaxf(m, __shfl_xor_sync(0xffffffffu, m, 8, 16));
    m = fmaxf(m, __shfl_xor_sync(0xffffffffu, m, 4, 16));
    m = fmaxf(m, __shfl_xor_sync(0xffffffffu, m, 2, 16));
    m = fmaxf(m, __shfl_xor_sync(0xffffffffu, m, 1, 16));
    float e = expf(s - m);
    float sum = e;
    sum += __shfl_xor_sync(0xffffffffu, sum, 8, 16);
    sum += __shfl_xor_sync(0xffffffffu, sum, 4, 16);
    sum += __shfl_xor_sync(0xffffffffu, sum, 2, 16);
    sum += __shfl_xor_sync(0xffffffffu, sum, 1, 16);
    g_attn[bh * 256 + threadIdx.x] = e / sum;
}

// ---------------------------------------------------------------------------
// 5) Effective proj weights: Weff[b][o][h*16+e] = sum_i proj_w[o][h*16+i]*attn[bh][i][e]
//    grid (4, 8) = (b, h), 256 threads
// ---------------------------------------------------------------------------
__global__ __launch_bounds__(256) void weff_k(const float* __restrict__ proj_w)
{
    int b = blockIdx.x, h = blockIdx.y;
    __shared__ float at[16][16];
    __shared__ float pw[128][16];
    int tid = threadIdx.x;

    at[tid >> 4][tid & 15] = g_attn[(b * 8 + h) * 256 + tid];
#pragma unroll
    for (int t = 0; t < 8; t++) {
        int idx = tid + t * 256;
        int o = idx >> 4, i = idx & 15;
        pw[o][i] = proj_w[o * 128 + h * 16 + i];
    }
    __syncthreads();

#pragma unroll
    for (int t = 0; t < 8; t++) {
        int idx = tid + t * 256;
        int o = idx >> 4, e = idx & 15;
        float s = 0.f;
#pragma unroll
        for (int i = 0; i < 16; i++) s = fmaf(pw[o][i], at[i][e], s);
        g_Weff[((size_t)b * 128 + o) * 128 + h * 16 + e] = s;
    }
}

// ---------------------------------------------------------------------------
// Launch
// ---------------------------------------------------------------------------
extern "C" void kernel_launch(void* const* d_in, const int* in_sizes, int n_in,
                              void* d_out, int out_size)
{
    const float* x      = (const float*)d_in[0];
    const float* ln1_w  = (const float*)d_in[1];
    const float* ln1_b  = (const float*)d_in[2];
    const float* temp   = (const float*)d_in[3];
    const float* qkv_pw = (const float*)d_in[4];
    const float* qkv_dw = (const float*)d_in[5];
    const float* proj_w = (const float*)d_in[6];
    const float* ln2_w  = (const float*)d_in[7];
    const float* ln2_b  = (const float*)d_in[8];
    const float* g1_w   = (const float*)d_in[9];
    const float* gd_w   = (const float*)d_in[10];
    const float* g2_w   = (const float*)d_in[11];
    float* out = (float*)d_out;

    float *bufA, *bufB, *WqP, *Wg1P, *rs, *cb, *Weff;
    cudaGetSymbolAddress((void**)&bufA, g_bufA);
    cudaGetSymbolAddress((void**)&bufB, g_bufB);
    cudaGetSymbolAddress((void**)&WqP,  g_WqP);
    cudaGetSymbolAddress((void**)&Wg1P, g_Wg1P);
    cudaGetSymbolAddress((void**)&rs,   g_rs);
    cudaGetSymbolAddress((void**)&cb,   g_cb);
    cudaGetSymbolAddress((void**)&Weff, g_Weff);

    dim3 b256(256);

    prep_w_k<<<112, b256>>>(qkv_pw, ln1_w, ln1_b, g1_w, ln2_w, ln2_b);

    // --- MDTA ---
    gemm_tc<1, false><<<dim3(HW / BN, 384 / BM, BATCH), b256>>>(
        WqP, x, rs, cb, nullptr, bufA, 384, 128, 128, 0);
    dwconv_k<<<dim3(4, 16, BATCH * 384), dim3(32, 8)>>>(bufA, qkv_dw, bufB, 384);
    attn_logits_k<<<dim3(ALOG_SEGS, 32), b256>>>(bufB);
    attn_finalize_k<<<32, b256>>>(temp);
    weff_k<<<dim3(4, 8), b256>>>(proj_w);
    // x2 = x + Weff_b * v   (v = channels 256..383 of bufB)
    gemm_tc<0, true><<<dim3(HW / BN, 1, BATCH), b256>>>(
        Weff, bufB + (size_t)256 * HW, nullptr, nullptr, x, out, 128, 128, 384, 128 * 128);

    // --- GDFN ---
    gemm_tc<1, false><<<dim3(HW / BN, 512 / BM, BATCH), b256>>>(
        Wg1P, out, rs + 384, cb + 384, nullptr, bufA, 512, 128, 128, 0);
    dwconv_k<<<dim3(4, 16, BATCH * 512), dim3(32, 8)>>>(bufA, gd_w, bufB, 512);
    gemm_tc<2, true><<<dim3(HW / BN, 1, BATCH), b256>>>(
        g2_w, bufB, nullptr, nullptr, out, out, 128, 256, 512, 0);
}